// round 1
// baseline (speedup 1.0000x reference)
#include <cuda_runtime.h>
#include <float.h>

// ---------------------------------------------------------------------------
// Problem shape (fixed by the reference)
// ---------------------------------------------------------------------------
#define M_Q   2048      // queries per coord set
#define N_P   32768     // graph nodes
#define D_F   256       // feature channels
#define D2    512       // 2*D

// ---------------------------------------------------------------------------
// Device scratch (no allocations allowed)
// ---------------------------------------------------------------------------
__device__ int   g_idx[4][M_Q];        // argmin indices per search
__device__ float g_partial[64][D_F];   // per-(side,chunk) max partials
__device__ float g_h[D2];              // fc1 output (post-relu)

// ---------------------------------------------------------------------------
// Kernel 1: brute-force NN argmin.
//   search 0: coords_orig vs pos0
//   search 1: coords_orig vs pos1
//   search 2: coords_mut  vs pos2
//   search 3: coords_mut  vs pos3
// argmin_p |q-p|^2 == argmin_p (|p|^2 - 2 q.p)   (|q|^2 constant per query)
// Grid: 256 blocks (64 per search). Block: 256 thr = 8 warps, 4 queries/warp.
// ---------------------------------------------------------------------------
#define NN_TILE 2048

__global__ __launch_bounds__(256)
void nn_kernel(const float* __restrict__ co, const float* __restrict__ cm,
               const float* __restrict__ p0, const float* __restrict__ p1,
               const float* __restrict__ p2, const float* __restrict__ p3)
{
    const int search = blockIdx.x >> 6;     // 0..3
    const int blk    = blockIdx.x & 63;     // 0..63 within search

    const float* __restrict__ q   = (search < 2) ? co : cm;
    const float* __restrict__ pos = (search == 0) ? p0 :
                                    (search == 1) ? p1 :
                                    (search == 2) ? p2 : p3;

    const int warp = threadIdx.x >> 5;
    const int lane = threadIdx.x & 31;
    const int qbase = blk * 32 + warp * 4;  // 4 queries per warp

    float n2x[4], n2y[4], n2z[4], best[4];
    int   bidx[4];
#pragma unroll
    for (int j = 0; j < 4; j++) {
        const int qi = qbase + j;
        n2x[j] = -2.0f * q[qi * 3 + 0];
        n2y[j] = -2.0f * q[qi * 3 + 1];
        n2z[j] = -2.0f * q[qi * 3 + 2];
        best[j] = FLT_MAX;
        bidx[j] = 0;
    }

    __shared__ float4 tile[NN_TILE];        // (x, y, z, |p|^2)

    for (int base = 0; base < N_P; base += NN_TILE) {
        __syncthreads();
        for (int i = threadIdx.x; i < NN_TILE; i += 256) {
            const float x = pos[(base + i) * 3 + 0];
            const float y = pos[(base + i) * 3 + 1];
            const float z = pos[(base + i) * 3 + 2];
            tile[i] = make_float4(x, y, z, fmaf(x, x, fmaf(y, y, z * z)));
        }
        __syncthreads();

        for (int i = lane; i < NN_TILE; i += 32) {
            const float4 p = tile[i];
#pragma unroll
            for (int j = 0; j < 4; j++) {
                float t = fmaf(p.x, n2x[j], p.w);
                t = fmaf(p.y, n2y[j], t);
                t = fmaf(p.z, n2z[j], t);
                if (t < best[j]) { best[j] = t; bidx[j] = base + i; }
            }
        }
    }

    // warp-level (min, first-index) reduction; queries are warp-exclusive
#pragma unroll
    for (int off = 16; off; off >>= 1) {
#pragma unroll
        for (int j = 0; j < 4; j++) {
            const float ob = __shfl_down_sync(0xffffffffu, best[j], off);
            const int   oi = __shfl_down_sync(0xffffffffu, bidx[j], off);
            if (ob < best[j] || (ob == best[j] && oi < bidx[j])) {
                best[j] = ob; bidx[j] = oi;
            }
        }
    }
    if (lane == 0) {
#pragma unroll
        for (int j = 0; j < 4; j++)
            g_idx[search][qbase + j] = bidx[j];
    }
}

// ---------------------------------------------------------------------------
// Kernel 2: gather feat rows, average left/right, max-pool over row chunk.
// Grid: 64 blocks = 2 sides x 32 chunks (64 rows each). 256 thr = channel.
// ---------------------------------------------------------------------------
__global__ __launch_bounds__(256)
void gather_max_kernel(const float* __restrict__ f0, const float* __restrict__ f1,
                       const float* __restrict__ f2, const float* __restrict__ f3)
{
    const int side  = blockIdx.x >> 5;   // 0 = orig, 1 = mut
    const int chunk = blockIdx.x & 31;
    const int c     = threadIdx.x;

    const float* __restrict__ fa = side ? f2 : f0;
    const float* __restrict__ fb = side ? f3 : f1;
    const int* __restrict__ ia = g_idx[side ? 2 : 0];
    const int* __restrict__ ib = g_idx[side ? 3 : 1];

    const int m0 = chunk * 64;
    float mx = -FLT_MAX;
#pragma unroll 4
    for (int m = m0; m < m0 + 64; m++) {
        const int ja = ia[m];
        const int jb = ib[m];
        const float v = 0.5f * (fa[ja * D_F + c] + fb[jb * D_F + c]);
        mx = fmaxf(mx, v);
    }
    g_partial[blockIdx.x][c] = mx;
}

// ---------------------------------------------------------------------------
// Kernel 3: finish max-pool -> x[512]; fc1 row j = relu(w1[j,:].x + b1[j]).
// Grid: 64 blocks x 256 thr; warp per output (8 outputs/block).
// x is recomputed per block from the 64KB partial buffer (L2-resident).
// ---------------------------------------------------------------------------
__global__ __launch_bounds__(256)
void fc1_kernel(const float* __restrict__ w1, const float* __restrict__ b1)
{
    __shared__ float xs[D2];

    for (int c = threadIdx.x; c < D2; c += 256) {
        const int side = c >> 8;
        const int cc   = c & 255;
        float mx = -FLT_MAX;
#pragma unroll
        for (int k = 0; k < 32; k++)
            mx = fmaxf(mx, g_partial[side * 32 + k][cc]);
        xs[c] = mx;
    }
    __syncthreads();

    const int warp = threadIdx.x >> 5;
    const int lane = threadIdx.x & 31;
    const int j = blockIdx.x * 8 + warp;

    float acc = 0.0f;
#pragma unroll
    for (int k = lane; k < D2; k += 32)
        acc = fmaf(w1[j * D2 + k], xs[k], acc);

#pragma unroll
    for (int off = 16; off; off >>= 1)
        acc += __shfl_down_sync(0xffffffffu, acc, off);

    if (lane == 0)
        g_h[j] = fmaxf(acc + b1[j], 0.0f);
}

// ---------------------------------------------------------------------------
// Kernel 4: fc2 scalar output.
// ---------------------------------------------------------------------------
__global__ __launch_bounds__(512)
void fc2_kernel(const float* __restrict__ w2, const float* __restrict__ b2,
                float* __restrict__ out)
{
    __shared__ float red[D2];
    red[threadIdx.x] = w2[threadIdx.x] * g_h[threadIdx.x];
    __syncthreads();
#pragma unroll
    for (int s = 256; s > 0; s >>= 1) {
        if (threadIdx.x < s) red[threadIdx.x] += red[threadIdx.x + s];
        __syncthreads();
    }
    if (threadIdx.x == 0)
        out[0] = red[0] + b2[0];
}

// ---------------------------------------------------------------------------
// Launch
// ---------------------------------------------------------------------------
extern "C" void kernel_launch(void* const* d_in, const int* in_sizes, int n_in,
                              void* d_out, int out_size)
{
    const float* co = (const float*)d_in[0];
    const float* cm = (const float*)d_in[1];
    const float* p0 = (const float*)d_in[2];
    const float* p1 = (const float*)d_in[3];
    const float* p2 = (const float*)d_in[4];
    const float* p3 = (const float*)d_in[5];
    const float* f0 = (const float*)d_in[6];
    const float* f1 = (const float*)d_in[7];
    const float* f2 = (const float*)d_in[8];
    const float* f3 = (const float*)d_in[9];
    const float* w1 = (const float*)d_in[10];
    const float* b1 = (const float*)d_in[11];
    const float* w2 = (const float*)d_in[12];
    const float* b2 = (const float*)d_in[13];
    float* out = (float*)d_out;

    nn_kernel<<<256, 256>>>(co, cm, p0, p1, p2, p3);
    gather_max_kernel<<<64, 256>>>(f0, f1, f2, f3);
    fc1_kernel<<<64, 256>>>(w1, b1);
    fc2_kernel<<<1, 512>>>(w2, b2, out);
}